// round 14
// baseline (speedup 1.0000x reference)
#include <cuda_runtime.h>
#include <cuda_bf16.h>
#include <math.h>

#define BATCH   4
#define C       512
#define HW      4096
#define NHEADS  4
#define HD      128
#define NGROUPS 32
#define EPS     1e-5f
// (1/sqrt(128)) * log2(e)
#define SCL2    0.12751743038311f

typedef unsigned u32;
typedef __nv_bfloat16  bf16;
typedef __nv_bfloat162 bf162;

// ---------------- scratch ----------------
__device__ float g_mean[BATCH * NGROUPS];
__device__ float g_rstd[BATCH * NGROUPS];
// normalized input bf16, layout [b][c][s]
__device__ __align__(16) bf16 g_xh[BATCH * C * HW];
// q/k/v bf16, layout [b][h][d][s]   (q pre-scaled by SCL2)
__device__ __align__(16) bf16 g_qh[BATCH * C * HW];
__device__ __align__(16) bf16 g_kh[BATCH * C * HW];
__device__ __align__(16) bf16 g_vh[BATCH * C * HW];
// attention out bf16, layout [b][c][s]
__device__ __align__(16) bf16 g_aoh[BATCH * C * HW];
// stacked bf16 weights: rows 0..511 wq | 512 wk | 1024 wv | 1536 wp
__device__ __align__(16) bf16 g_wh[2048 * C];

// ---------------- helpers ----------------
__device__ __forceinline__ u32 smaddr(const void* p) {
    return (u32)__cvta_generic_to_shared(p);
}
__device__ __forceinline__ void cpa16(u32 dst, const void* src) {
    asm volatile("cp.async.cg.shared.global [%0], [%1], 16;" :: "r"(dst), "l"(src));
}
__device__ __forceinline__ void cpa_commit() {
    asm volatile("cp.async.commit_group;");
}
template <int N>
__device__ __forceinline__ void cpa_wait() {
    asm volatile("cp.async.wait_group %0;" :: "n"(N));
}
__device__ __forceinline__ void ldsm4(u32* r, u32 a) {
    asm volatile("ldmatrix.sync.aligned.m8n8.x4.shared.b16 {%0,%1,%2,%3},[%4];"
        : "=r"(r[0]), "=r"(r[1]), "=r"(r[2]), "=r"(r[3]) : "r"(a));
}
__device__ __forceinline__ void ldsm4t(u32* r, u32 a) {
    asm volatile("ldmatrix.sync.aligned.m8n8.x4.trans.shared.b16 {%0,%1,%2,%3},[%4];"
        : "=r"(r[0]), "=r"(r[1]), "=r"(r[2]), "=r"(r[3]) : "r"(a));
}
__device__ __forceinline__ void mma(float* d, const u32* a, const u32* b) {
    asm volatile("mma.sync.aligned.m16n8k16.row.col.f32.bf16.bf16.f32 "
        "{%0,%1,%2,%3},{%4,%5,%6,%7},{%8,%9},{%0,%1,%2,%3};"
        : "+f"(d[0]), "+f"(d[1]), "+f"(d[2]), "+f"(d[3])
        : "r"(a[0]), "r"(a[1]), "r"(a[2]), "r"(a[3]), "r"(b[0]), "r"(b[1]));
}
__device__ __forceinline__ u32 packbf(float a, float b) {
    bf162 t = __floats2bfloat162_rn(a, b);
    return *(u32*)&t;
}
__device__ __forceinline__ float ex2(float x) {
    float r; asm("ex2.approx.f32 %0, %1;" : "=f"(r) : "f"(x)); return r;
}

// ---------------- GroupNorm statistics ----------------
__global__ void __launch_bounds__(256) gn_stats_kernel(const float* __restrict__ x) {
    const int bg = blockIdx.x;
    const float4* p = (const float4*)(x + (size_t)bg * (16 * HW));
    float s = 0.f, s2 = 0.f;
    for (int i = threadIdx.x; i < (16 * HW) / 4; i += 256) {
        float4 v = p[i];
        s  += (v.x + v.y) + (v.z + v.w);
        s2 += v.x*v.x + v.y*v.y + v.z*v.z + v.w*v.w;
    }
    #pragma unroll
    for (int off = 16; off; off >>= 1) {
        s  += __shfl_xor_sync(0xffffffffu, s,  off);
        s2 += __shfl_xor_sync(0xffffffffu, s2, off);
    }
    __shared__ float ss[8], ss2[8];
    const int w = threadIdx.x >> 5, l = threadIdx.x & 31;
    if (l == 0) { ss[w] = s; ss2[w] = s2; }
    __syncthreads();
    if (threadIdx.x == 0) {
        float S = 0.f, S2 = 0.f;
        #pragma unroll
        for (int i = 0; i < 8; i++) { S += ss[i]; S2 += ss2[i]; }
        const float inv = 1.f / (16.f * HW);
        float mean = S * inv;
        float var  = S2 * inv - mean * mean;
        g_mean[bg] = mean;
        g_rstd[bg] = rsqrtf(var + EPS);
    }
}

// ---------------- weight convert (bf16) ----------------
__global__ void __launch_bounds__(256) wprep_kernel(
    const float* __restrict__ wq, const float* __restrict__ wk,
    const float* __restrict__ wv, const float* __restrict__ wp)
{
    int i = blockIdx.x * 256 + threadIdx.x;    // 2048*512
    int r = i >> 9, c = i & 511;
    const float* srcs[4] = {wq, wk, wv, wp};
    float v = srcs[r >> 9][(r & 511) * C + c];
    g_wh[i] = __float2bfloat16(v);
}

// ---------------- normalize x -> bf16 ----------------
__global__ void __launch_bounds__(256) xnorm_kernel(
    const float* __restrict__ x,
    const float* __restrict__ gnw, const float* __restrict__ gnb)
{
    const int bc = blockIdx.x;                // b*C + c
    const int b = bc >> 9, c = bc & 511;
    const int grp = c >> 4;
    const float mu = g_mean[b * NGROUPS + grp], rs = g_rstd[b * NGROUPS + grp];
    const float sc = rs * gnw[c], sh = gnb[c] - mu * sc;
    const float* xp = x + (size_t)bc * HW;
    bf16* oh = g_xh + (size_t)bc * HW;
    for (int i = threadIdx.x * 4; i < HW; i += 1024) {
        float4 v = *(const float4*)(xp + i);
        uint2 H;
        H.x = packbf(fmaf(v.x, sc, sh), fmaf(v.y, sc, sh));
        H.y = packbf(fmaf(v.z, sc, sh), fmaf(v.w, sc, sh));
        *(uint2*)(oh + i) = H;
    }
}

// ---------------- conv GEMM: 128m x 64n tile, 128 thr, 4+ CTAs/SM ----------
// stage layout: Ah 10240 | Bh 4096 = 14336 B
#define CONV_STAGE 14336
#define CONV_SMEM  (2 * CONV_STAGE)

template <int EPI>
__global__ void __launch_bounds__(128) conv_mma_kernel(
    const bf16* __restrict__ BH,
    const float* __restrict__ bq, const float* __restrict__ bk,
    const float* __restrict__ bv, const float* __restrict__ bp,
    const float* __restrict__ resid, float* __restrict__ outp)
{
    extern __shared__ char smem[];
    const int tid = threadIdx.x, lane = tid & 31, wm = tid >> 5;  // 4 warps, wm 0..3
    const int b = blockIdx.z;
    const int oBase = (EPI ? 1536 : 0) + blockIdx.y * 128;
    const int sBase = blockIdx.x * 64;

    auto load_stage = [&](int kb, int s) {
        char* Ah = smem + s * CONV_STAGE;
        char* Bh = Ah + 10240;
        #pragma unroll
        for (int ch = tid; ch < 512; ch += 128) {
            int row = ch >> 2, g = ch & 3;
            size_t ga = (size_t)(oBase + row) * C + kb + g * 8;
            cpa16(smaddr(Ah + row * 80 + g * 16), g_wh + ga);
        }
        #pragma unroll
        for (int ch = tid; ch < 256; ch += 128) {
            int k = ch >> 3, g = ch & 7;      // 32 k rows, 8 chunks of 8 cols
            size_t ga = ((size_t)b * C + kb + k) * HW + sBase + g * 8;
            u32 d = k * 128 + (((g ^ (k & 7)) & 7) << 4);
            cpa16(smaddr(Bh + d), BH + ga);
        }
    };

    float acc[2][8][4];
    #pragma unroll
    for (int mt = 0; mt < 2; mt++)
        #pragma unroll
        for (int nt = 0; nt < 8; nt++)
            #pragma unroll
            for (int i = 0; i < 4; i++) acc[mt][nt][i] = 0.f;

    load_stage(0, 0);
    cpa_commit();

    for (int it = 0; it < 16; it++) {
        if (it + 1 < 16) load_stage((it + 1) * 32, (it + 1) & 1);
        cpa_commit();
        cpa_wait<1>();
        __syncthreads();

        char* Ah = smem + (it & 1) * CONV_STAGE;
        char* Bh = Ah + 10240;

        #pragma unroll
        for (int kk = 0; kk < 32; kk += 16) {
            u32 ah[2][4];
            #pragma unroll
            for (int mt = 0; mt < 2; mt++) {
                int row = wm * 32 + mt * 16 + (lane & 15);
                u32 off = row * 80 + ((kk >> 3) + (lane >> 4)) * 16;
                ldsm4(ah[mt], smaddr(Ah + off));
            }
            #pragma unroll
            for (int ng = 0; ng < 4; ng++) {
                int row = kk + ((lane >> 3) & 1) * 8 + (lane & 7);
                int nc  = ng * 16 + ((lane >> 4) & 1) * 8;
                u32 off = row * 128 + ((((nc >> 3) ^ (row & 7)) & 7) << 4);
                u32 bh_[4];
                ldsm4t(bh_, smaddr(Bh + off));
                #pragma unroll
                for (int mt = 0; mt < 2; mt++) {
                    mma(acc[mt][2 * ng],     ah[mt], &bh_[0]);
                    mma(acc[mt][2 * ng + 1], ah[mt], &bh_[2]);
                }
            }
        }
        __syncthreads();
    }

    // epilogue
    const int gr = lane >> 2, c2 = (lane & 3) * 2;
    if constexpr (EPI == 0) {
        const int mat  = blockIdx.y >> 2;
        const int head = blockIdx.y & 3;
        bf16* DH = (mat == 0) ? g_qh : (mat == 1) ? g_kh : g_vh;
        const float* bias = (mat == 0) ? bq : (mat == 1) ? bk : bv;
        const float osc = (mat == 0) ? SCL2 : 1.0f;    // fold softmax scale into q
        const size_t hb = (size_t)(b * NHEADS + head) * HD * HW;
        #pragma unroll
        for (int mt = 0; mt < 2; mt++) {
            int d0 = wm * 32 + mt * 16 + gr;
            float bs0 = bias[head * HD + d0];
            float bs1 = bias[head * HD + d0 + 8];
            #pragma unroll
            for (int nt = 0; nt < 8; nt++) {
                int s = sBase + nt * 8 + c2;
                *(u32*)(DH + hb + (size_t)d0 * HW + s) =
                    packbf((acc[mt][nt][0] + bs0) * osc, (acc[mt][nt][1] + bs0) * osc);
                *(u32*)(DH + hb + (size_t)(d0 + 8) * HW + s) =
                    packbf((acc[mt][nt][2] + bs1) * osc, (acc[mt][nt][3] + bs1) * osc);
            }
        }
    } else {
        const int cB = blockIdx.y * 128;
        #pragma unroll
        for (int mt = 0; mt < 2; mt++) {
            int ca = cB + wm * 32 + mt * 16 + gr;
            float bsa = bp[ca], bsb = bp[ca + 8];
            #pragma unroll
            for (int nt = 0; nt < 8; nt++) {
                int s = sBase + nt * 8 + c2;
                size_t ia = ((size_t)b * C + ca) * HW + s;
                size_t ib = ia + (size_t)8 * HW;
                float2 ra = *(const float2*)(resid + ia);
                float2 rb = *(const float2*)(resid + ib);
                *(float2*)(outp + ia) = make_float2(acc[mt][nt][0] + bsa + ra.x,
                                                    acc[mt][nt][1] + bsa + ra.y);
                *(float2*)(outp + ib) = make_float2(acc[mt][nt][2] + bsb + rb.x,
                                                    acc[mt][nt][3] + bsb + rb.y);
            }
        }
    }
}

// ---------------- flash attention: 64-row Q, 128 thr, 3-stage, 2 CTAs/SM ---
// smem: Qh 16K | stage0 32K | stage1 32K | stage2 32K = 112K
// stage: Kh 16K | Vh 16K
#define ATT_STAGE 32768
#define ATT_SMEM  (16384 + 3 * ATT_STAGE)
#define NKT       (HW / 64)

__global__ void __launch_bounds__(128) attn_mma_kernel() {
    extern __shared__ char sm[];
    char* sQh = sm;

    const int tid = threadIdx.x, lane = tid & 31, wid = tid >> 5;   // wid 0..3
    const int qt = blockIdx.x, h = blockIdx.y, b = blockIdx.z;
    const size_t hb = (size_t)(b * NHEADS + h) * HD * HW;
    const int s0q = qt * 64;

    auto load_kv = [&](int kt, int s) {
        char* Kh = sm + 16384 + s * ATT_STAGE;
        char* Vh = Kh + 16384;
        #pragma unroll
        for (int ch = tid; ch < 1024; ch += 128) {
            int d = ch >> 3, g = ch & 7;
            size_t ga = hb + (size_t)d * HW + kt * 64 + g * 8;
            u32 off = d * 128 + (((g ^ (d & 7)) & 7) << 4);
            cpa16(smaddr(Kh + off), g_kh + ga);
            cpa16(smaddr(Vh + off), g_vh + ga);
        }
    };

    // group 0: Q + kv0 ; group 1: kv1
    #pragma unroll
    for (int ch = tid; ch < 1024; ch += 128) {
        int d = ch >> 3, g = ch & 7;
        size_t ga = hb + (size_t)d * HW + s0q + g * 8;
        u32 off = d * 128 + (((g ^ (d & 7)) & 7) << 4);
        cpa16(smaddr(sQh + off), g_qh + ga);
    }
    load_kv(0, 0);
    cpa_commit();
    load_kv(1, 1);
    cpa_commit();

    cpa_wait<1>();
    __syncthreads();

    // hoist Q fragments (A of S; m = 16 rows per warp)
    u32 qf[8][4];
    {
        int mc = wid * 16 + ((lane >> 3) & 1) * 8;
        #pragma unroll
        for (int ks = 0; ks < 8; ks++) {
            int rq = ks * 16 + (lane & 7) + ((lane >> 4) & 1) * 8;
            u32 qoff = rq * 128 + ((((mc >> 3) ^ (rq & 7)) & 7) << 4);
            ldsm4t(qf[ks], smaddr(sQh + qoff));
        }
    }

    float oac[16][4];
    #pragma unroll
    for (int nt = 0; nt < 16; nt++)
        #pragma unroll
        for (int i = 0; i < 4; i++) oac[nt][i] = 0.f;
    float l0r = 0.f, l1r = 0.f;

    for (int kt = 0; kt < NKT; kt++) {
        if (kt + 2 < NKT) load_kv(kt + 2, (kt + 2) % 3);
        cpa_commit();
        cpa_wait<2>();
        __syncthreads();

        char* Kh = sm + 16384 + (kt % 3) * ATT_STAGE;
        char* Vh = Kh + 16384;

        // ---- S = Q K^T (q pre-scaled, bf16) ----
        float sacc[8][4];
        #pragma unroll
        for (int nt = 0; nt < 8; nt++)
            #pragma unroll
            for (int i = 0; i < 4; i++) sacc[nt][i] = 0.f;

        #pragma unroll
        for (int ks = 0; ks < 8; ks++) {
            int rk = ks * 16 + ((lane >> 3) & 1) * 8 + (lane & 7);
            int ncb = ((lane >> 4) & 1) * 8;
            #pragma unroll
            for (int ng = 0; ng < 4; ng++) {
                int nc = ng * 16 + ncb;
                u32 koff = rk * 128 + ((((nc >> 3) ^ (rk & 7)) & 7) << 4);
                u32 kh_[4];
                ldsm4t(kh_, smaddr(Kh + koff));
                mma(sacc[2 * ng],     qf[ks], &kh_[0]);
                mma(sacc[2 * ng + 1], qf[ks], &kh_[2]);
            }
        }

        // ---- softmax, static max (p = 2^s) ----
        u32 ph[8][2];
        #pragma unroll
        for (int nt = 0; nt < 8; nt++) {
            float p0 = ex2(sacc[nt][0]);
            float p1 = ex2(sacc[nt][1]);
            float p2 = ex2(sacc[nt][2]);
            float p3 = ex2(sacc[nt][3]);
            l0r += p0 + p1; l1r += p2 + p3;
            ph[nt][0] = packbf(p0, p1);
            ph[nt][1] = packbf(p2, p3);
        }

        // ---- O += P V ----
        #pragma unroll
        for (int ks2 = 0; ks2 < 4; ks2++) {
            u32 pah[4] = {ph[2*ks2][0], ph[2*ks2][1], ph[2*ks2+1][0], ph[2*ks2+1][1]};
            int kc = ks2 * 16 + ((lane >> 3) & 1) * 8;
            int rvb = ((lane >> 4) & 1) * 8 + (lane & 7);
            #pragma unroll
            for (int nd = 0; nd < 8; nd++) {
                int rv = nd * 16 + rvb;
                u32 voff = rv * 128 + ((((kc >> 3) ^ (rv & 7)) & 7) << 4);
                u32 vh_[4];
                ldsm4(vh_, smaddr(Vh + voff));
                mma(oac[2 * nd],     pah, &vh_[0]);
                mma(oac[2 * nd + 1], pah, &vh_[2]);
            }
        }
        __syncthreads();
    }

    // ---- row-sum reduction (once) ----
    l0r += __shfl_xor_sync(0xffffffffu, l0r, 1);
    l0r += __shfl_xor_sync(0xffffffffu, l0r, 2);
    l1r += __shfl_xor_sync(0xffffffffu, l1r, 1);
    l1r += __shfl_xor_sync(0xffffffffu, l1r, 2);

    // ---- normalize + transpose (reuse stage smem) + store bf16 ----
    float inv0 = 1.f / l0r, inv1 = 1.f / l1r;
    float* Osm = (float*)(sm + 16384);  // [64 s][64 d] pitch 65 (16.6KB)
    const int r0 = wid * 16 + (lane >> 2), c2 = (lane & 3) * 2;
    #pragma unroll
    for (int dh = 0; dh < 2; dh++) {
        __syncthreads();
        #pragma unroll
        for (int j = 0; j < 8; j++) {
            int nt = dh * 8 + j;
            int dloc = j * 8 + c2;
            Osm[r0 * 65 + dloc]           = oac[nt][0] * inv0;
            Osm[r0 * 65 + dloc + 1]       = oac[nt][1] * inv0;
            Osm[(r0 + 8) * 65 + dloc]     = oac[nt][2] * inv1;
            Osm[(r0 + 8) * 65 + dloc + 1] = oac[nt][3] * inv1;
        }
        __syncthreads();
        for (int ch = tid; ch < 512; ch += 128) {
            int dl = ch >> 3, g = ch & 7;
            float f[8];
            #pragma unroll
            for (int j = 0; j < 8; j++) f[j] = Osm[(g * 8 + j) * 65 + dl];
            uint4 H;
            H.x = packbf(f[0], f[1]);
            H.y = packbf(f[2], f[3]);
            H.z = packbf(f[4], f[5]);
            H.w = packbf(f[6], f[7]);
            int c = h * 128 + dh * 64 + dl;
            size_t ga = ((size_t)b * C + c) * HW + s0q + g * 8;
            *(uint4*)(g_aoh + ga) = H;
        }
    }
}

// ---------------- launch ----------------
extern "C" void kernel_launch(void* const* d_in, const int* in_sizes, int n_in,
                              void* d_out, int out_size) {
    const float* x   = (const float*)d_in[0];
    const float* gnw = (const float*)d_in[1];
    const float* gnb = (const float*)d_in[2];
    const float* wq  = (const float*)d_in[3];
    const float* bq  = (const float*)d_in[4];
    const float* wk  = (const float*)d_in[5];
    const float* bk  = (const float*)d_in[6];
    const float* wv  = (const float*)d_in[7];
    const float* bv  = (const float*)d_in[8];
    const float* wp  = (const float*)d_in[9];
    const float* bp  = (const float*)d_in[10];
    float* out = (float*)d_out;

    cudaFuncSetAttribute(attn_mma_kernel,
                         cudaFuncAttributeMaxDynamicSharedMemorySize, ATT_SMEM);
    cudaFuncSetAttribute(conv_mma_kernel<0>,
                         cudaFuncAttributeMaxDynamicSharedMemorySize, CONV_SMEM);
    cudaFuncSetAttribute(conv_mma_kernel<1>,
                         cudaFuncAttributeMaxDynamicSharedMemorySize, CONV_SMEM);

    bf16 *d_xh, *d_aoh;
    cudaGetSymbolAddress((void**)&d_xh,  g_xh);
    cudaGetSymbolAddress((void**)&d_aoh, g_aoh);

    gn_stats_kernel<<<BATCH * NGROUPS, 256>>>(x);
    wprep_kernel<<<4096, 256>>>(wq, wk, wv, wp);
    xnorm_kernel<<<BATCH * C, 256>>>(x, gnw, gnb);
    conv_mma_kernel<0><<<dim3(HW / 64, 12, BATCH), 128, CONV_SMEM>>>(
        d_xh, bq, bk, bv, bp, x, nullptr);
    attn_mma_kernel<<<dim3(HW / 64, NHEADS, BATCH), 128, ATT_SMEM>>>();
    conv_mma_kernel<1><<<dim3(HW / 64, 4, BATCH), 128, CONV_SMEM>>>(
        d_aoh, bq, bk, bv, bp, x, out);
}

// round 15
// speedup vs baseline: 1.0753x; 1.0753x over previous
#include <cuda_runtime.h>
#include <cuda_bf16.h>
#include <math.h>

#define BATCH   4
#define C       512
#define HW      4096
#define NHEADS  4
#define HD      128
#define NGROUPS 32
#define EPS     1e-5f
// (1/sqrt(128)) * log2(e)
#define SCL2    0.12751743038311f

typedef unsigned u32;
typedef __nv_bfloat16  bf16;
typedef __nv_bfloat162 bf162;

// ---------------- scratch ----------------
__device__ float g_mean[BATCH * NGROUPS];
__device__ float g_rstd[BATCH * NGROUPS];
// normalized input bf16, layout [b][c][s]
__device__ __align__(16) bf16 g_xh[BATCH * C * HW];
// q/k/v bf16, layout [b][h][d][s]   (q pre-scaled by SCL2)
__device__ __align__(16) bf16 g_qh[BATCH * C * HW];
__device__ __align__(16) bf16 g_kh[BATCH * C * HW];
__device__ __align__(16) bf16 g_vh[BATCH * C * HW];
// attention out bf16, layout [b][c][s]
__device__ __align__(16) bf16 g_aoh[BATCH * C * HW];
// stacked bf16 weights: rows 0..511 wq | 512 wk | 1024 wv | 1536 wp
__device__ __align__(16) bf16 g_wh[2048 * C];

// ---------------- helpers ----------------
__device__ __forceinline__ u32 smaddr(const void* p) {
    return (u32)__cvta_generic_to_shared(p);
}
__device__ __forceinline__ void cpa16(u32 dst, const void* src) {
    asm volatile("cp.async.cg.shared.global [%0], [%1], 16;" :: "r"(dst), "l"(src));
}
__device__ __forceinline__ void cpa_commit() {
    asm volatile("cp.async.commit_group;");
}
template <int N>
__device__ __forceinline__ void cpa_wait() {
    asm volatile("cp.async.wait_group %0;" :: "n"(N));
}
__device__ __forceinline__ void ldsm4(u32* r, u32 a) {
    asm volatile("ldmatrix.sync.aligned.m8n8.x4.shared.b16 {%0,%1,%2,%3},[%4];"
        : "=r"(r[0]), "=r"(r[1]), "=r"(r[2]), "=r"(r[3]) : "r"(a));
}
__device__ __forceinline__ void ldsm4t(u32* r, u32 a) {
    asm volatile("ldmatrix.sync.aligned.m8n8.x4.trans.shared.b16 {%0,%1,%2,%3},[%4];"
        : "=r"(r[0]), "=r"(r[1]), "=r"(r[2]), "=r"(r[3]) : "r"(a));
}
__device__ __forceinline__ void mma(float* d, const u32* a, const u32* b) {
    asm volatile("mma.sync.aligned.m16n8k16.row.col.f32.bf16.bf16.f32 "
        "{%0,%1,%2,%3},{%4,%5,%6,%7},{%8,%9},{%0,%1,%2,%3};"
        : "+f"(d[0]), "+f"(d[1]), "+f"(d[2]), "+f"(d[3])
        : "r"(a[0]), "r"(a[1]), "r"(a[2]), "r"(a[3]), "r"(b[0]), "r"(b[1]));
}
__device__ __forceinline__ u32 packbf(float a, float b) {
    bf162 t = __floats2bfloat162_rn(a, b);
    return *(u32*)&t;
}
__device__ __forceinline__ float ex2(float x) {
    float r; asm("ex2.approx.f32 %0, %1;" : "=f"(r) : "f"(x)); return r;
}

// ---------------- GroupNorm statistics ----------------
__global__ void __launch_bounds__(256) gn_stats_kernel(const float* __restrict__ x) {
    const int bg = blockIdx.x;
    const float4* p = (const float4*)(x + (size_t)bg * (16 * HW));
    float s = 0.f, s2 = 0.f;
    for (int i = threadIdx.x; i < (16 * HW) / 4; i += 256) {
        float4 v = p[i];
        s  += (v.x + v.y) + (v.z + v.w);
        s2 += v.x*v.x + v.y*v.y + v.z*v.z + v.w*v.w;
    }
    #pragma unroll
    for (int off = 16; off; off >>= 1) {
        s  += __shfl_xor_sync(0xffffffffu, s,  off);
        s2 += __shfl_xor_sync(0xffffffffu, s2, off);
    }
    __shared__ float ss[8], ss2[8];
    const int w = threadIdx.x >> 5, l = threadIdx.x & 31;
    if (l == 0) { ss[w] = s; ss2[w] = s2; }
    __syncthreads();
    if (threadIdx.x == 0) {
        float S = 0.f, S2 = 0.f;
        #pragma unroll
        for (int i = 0; i < 8; i++) { S += ss[i]; S2 += ss2[i]; }
        const float inv = 1.f / (16.f * HW);
        float mean = S * inv;
        float var  = S2 * inv - mean * mean;
        g_mean[bg] = mean;
        g_rstd[bg] = rsqrtf(var + EPS);
    }
}

// ---------------- weight convert (bf16) ----------------
__global__ void __launch_bounds__(256) wprep_kernel(
    const float* __restrict__ wq, const float* __restrict__ wk,
    const float* __restrict__ wv, const float* __restrict__ wp)
{
    int i = blockIdx.x * 256 + threadIdx.x;    // 2048*512
    int r = i >> 9, c = i & 511;
    const float* srcs[4] = {wq, wk, wv, wp};
    float v = srcs[r >> 9][(r & 511) * C + c];
    g_wh[i] = __float2bfloat16(v);
}

// ---------------- normalize x -> bf16 ----------------
__global__ void __launch_bounds__(256) xnorm_kernel(
    const float* __restrict__ x,
    const float* __restrict__ gnw, const float* __restrict__ gnb)
{
    const int bc = blockIdx.x;                // b*C + c
    const int b = bc >> 9, c = bc & 511;
    const int grp = c >> 4;
    const float mu = g_mean[b * NGROUPS + grp], rs = g_rstd[b * NGROUPS + grp];
    const float sc = rs * gnw[c], sh = gnb[c] - mu * sc;
    const float* xp = x + (size_t)bc * HW;
    bf16* oh = g_xh + (size_t)bc * HW;
    for (int i = threadIdx.x * 4; i < HW; i += 1024) {
        float4 v = *(const float4*)(xp + i);
        uint2 H;
        H.x = packbf(fmaf(v.x, sc, sh), fmaf(v.y, sc, sh));
        H.y = packbf(fmaf(v.z, sc, sh), fmaf(v.w, sc, sh));
        *(uint2*)(oh + i) = H;
    }
}

// ---------------- conv GEMM: 128m x 64n tile, 128 thr ----------------------
// stage layout: Ah 10240 | Bh 4096 = 14336 B
#define CONV_STAGE 14336
#define CONV_SMEM  (2 * CONV_STAGE)

template <int EPI>
__global__ void __launch_bounds__(128) conv_mma_kernel(
    const bf16* __restrict__ BH,
    const float* __restrict__ bq, const float* __restrict__ bk,
    const float* __restrict__ bv, const float* __restrict__ bp,
    const float* __restrict__ resid, float* __restrict__ outp)
{
    extern __shared__ char smem[];
    const int tid = threadIdx.x, lane = tid & 31, wm = tid >> 5;  // 4 warps
    const int b = blockIdx.z;
    const int oBase = (EPI ? 1536 : 0) + blockIdx.y * 128;
    const int sBase = blockIdx.x * 64;

    auto load_stage = [&](int kb, int s) {
        char* Ah = smem + s * CONV_STAGE;
        char* Bh = Ah + 10240;
        #pragma unroll
        for (int ch = tid; ch < 512; ch += 128) {
            int row = ch >> 2, g = ch & 3;
            size_t ga = (size_t)(oBase + row) * C + kb + g * 8;
            cpa16(smaddr(Ah + row * 80 + g * 16), g_wh + ga);
        }
        #pragma unroll
        for (int ch = tid; ch < 256; ch += 128) {
            int k = ch >> 3, g = ch & 7;
            size_t ga = ((size_t)b * C + kb + k) * HW + sBase + g * 8;
            u32 d = k * 128 + (((g ^ (k & 7)) & 7) << 4);
            cpa16(smaddr(Bh + d), BH + ga);
        }
    };

    float acc[2][8][4];
    #pragma unroll
    for (int mt = 0; mt < 2; mt++)
        #pragma unroll
        for (int nt = 0; nt < 8; nt++)
            #pragma unroll
            for (int i = 0; i < 4; i++) acc[mt][nt][i] = 0.f;

    load_stage(0, 0);
    cpa_commit();

    for (int it = 0; it < 16; it++) {
        if (it + 1 < 16) load_stage((it + 1) * 32, (it + 1) & 1);
        cpa_commit();
        cpa_wait<1>();
        __syncthreads();

        char* Ah = smem + (it & 1) * CONV_STAGE;
        char* Bh = Ah + 10240;

        #pragma unroll
        for (int kk = 0; kk < 32; kk += 16) {
            u32 ah[2][4];
            #pragma unroll
            for (int mt = 0; mt < 2; mt++) {
                int row = wm * 32 + mt * 16 + (lane & 15);
                u32 off = row * 80 + ((kk >> 3) + (lane >> 4)) * 16;
                ldsm4(ah[mt], smaddr(Ah + off));
            }
            #pragma unroll
            for (int ng = 0; ng < 4; ng++) {
                int row = kk + ((lane >> 3) & 1) * 8 + (lane & 7);
                int nc  = ng * 16 + ((lane >> 4) & 1) * 8;
                u32 off = row * 128 + ((((nc >> 3) ^ (row & 7)) & 7) << 4);
                u32 bh_[4];
                ldsm4t(bh_, smaddr(Bh + off));
                #pragma unroll
                for (int mt = 0; mt < 2; mt++) {
                    mma(acc[mt][2 * ng],     ah[mt], &bh_[0]);
                    mma(acc[mt][2 * ng + 1], ah[mt], &bh_[2]);
                }
            }
        }
        __syncthreads();
    }

    // epilogue
    const int gr = lane >> 2, c2 = (lane & 3) * 2;
    if constexpr (EPI == 0) {
        const int mat  = blockIdx.y >> 2;
        const int head = blockIdx.y & 3;
        bf16* DH = (mat == 0) ? g_qh : (mat == 1) ? g_kh : g_vh;
        const float* bias = (mat == 0) ? bq : (mat == 1) ? bk : bv;
        const float osc = (mat == 0) ? SCL2 : 1.0f;    // fold softmax scale into q
        const size_t hb = (size_t)(b * NHEADS + head) * HD * HW;
        #pragma unroll
        for (int mt = 0; mt < 2; mt++) {
            int d0 = wm * 32 + mt * 16 + gr;
            float bs0 = bias[head * HD + d0];
            float bs1 = bias[head * HD + d0 + 8];
            #pragma unroll
            for (int nt = 0; nt < 8; nt++) {
                int s = sBase + nt * 8 + c2;
                *(u32*)(DH + hb + (size_t)d0 * HW + s) =
                    packbf((acc[mt][nt][0] + bs0) * osc, (acc[mt][nt][1] + bs0) * osc);
                *(u32*)(DH + hb + (size_t)(d0 + 8) * HW + s) =
                    packbf((acc[mt][nt][2] + bs1) * osc, (acc[mt][nt][3] + bs1) * osc);
            }
        }
    } else {
        const int cB = blockIdx.y * 128;
        #pragma unroll
        for (int mt = 0; mt < 2; mt++) {
            int ca = cB + wm * 32 + mt * 16 + gr;
            float bsa = bp[ca], bsb = bp[ca + 8];
            #pragma unroll
            for (int nt = 0; nt < 8; nt++) {
                int s = sBase + nt * 8 + c2;
                size_t ia = ((size_t)b * C + ca) * HW + s;
                size_t ib = ia + (size_t)8 * HW;
                float2 ra = *(const float2*)(resid + ia);
                float2 rb = *(const float2*)(resid + ib);
                *(float2*)(outp + ia) = make_float2(acc[mt][nt][0] + bsa + ra.x,
                                                    acc[mt][nt][1] + bsa + ra.y);
                *(float2*)(outp + ib) = make_float2(acc[mt][nt][2] + bsb + rb.x,
                                                    acc[mt][nt][3] + bsb + rb.y);
            }
        }
    }
}

// ---------------- flash attention: 64-row Q, 128 thr, 2-stage, 2 CTAs/SM ---
// smem: Qh 16K | stage0 32K | stage1 32K = 80K
// stage: Kh 16K | Vh 16K
#define ATT_STAGE 32768
#define ATT_SMEM  (16384 + 2 * ATT_STAGE)
#define NKT       (HW / 64)

__global__ void __launch_bounds__(128) attn_mma_kernel() {
    extern __shared__ char sm[];
    char* sQh = sm;

    const int tid = threadIdx.x, lane = tid & 31, wid = tid >> 5;   // wid 0..3
    const int qt = blockIdx.x, h = blockIdx.y, b = blockIdx.z;
    const size_t hb = (size_t)(b * NHEADS + h) * HD * HW;
    const int s0q = qt * 64;

    auto load_kv = [&](int kt, int s) {
        char* Kh = sm + 16384 + s * ATT_STAGE;
        char* Vh = Kh + 16384;
        #pragma unroll
        for (int ch = tid; ch < 1024; ch += 128) {
            int d = ch >> 3, g = ch & 7;
            size_t ga = hb + (size_t)d * HW + kt * 64 + g * 8;
            u32 off = d * 128 + (((g ^ (d & 7)) & 7) << 4);
            cpa16(smaddr(Kh + off), g_kh + ga);
            cpa16(smaddr(Vh + off), g_vh + ga);
        }
    };

    // group 0: Q + kv0
    #pragma unroll
    for (int ch = tid; ch < 1024; ch += 128) {
        int d = ch >> 3, g = ch & 7;
        size_t ga = hb + (size_t)d * HW + s0q + g * 8;
        u32 off = d * 128 + (((g ^ (d & 7)) & 7) << 4);
        cpa16(smaddr(sQh + off), g_qh + ga);
    }
    load_kv(0, 0);
    cpa_commit();

    cpa_wait<0>();
    __syncthreads();

    // hoist Q fragments (A of S; m = 16 rows per warp)
    u32 qf[8][4];
    {
        int mc = wid * 16 + ((lane >> 3) & 1) * 8;
        #pragma unroll
        for (int ks = 0; ks < 8; ks++) {
            int rq = ks * 16 + (lane & 7) + ((lane >> 4) & 1) * 8;
            u32 qoff = rq * 128 + ((((mc >> 3) ^ (rq & 7)) & 7) << 4);
            ldsm4t(qf[ks], smaddr(sQh + qoff));
        }
    }

    float oac[16][4];
    #pragma unroll
    for (int nt = 0; nt < 16; nt++)
        #pragma unroll
        for (int i = 0; i < 4; i++) oac[nt][i] = 0.f;
    float l0r = 0.f, l1r = 0.f;

    for (int kt = 0; kt < NKT; kt++) {
        if (kt + 1 < NKT) load_kv(kt + 1, (kt + 1) & 1);
        cpa_commit();
        cpa_wait<1>();
        __syncthreads();

        char* Kh = sm + 16384 + (kt & 1) * ATT_STAGE;
        char* Vh = Kh + 16384;

        // ---- S = Q K^T (q pre-scaled, bf16) ----
        float sacc[8][4];
        #pragma unroll
        for (int nt = 0; nt < 8; nt++)
            #pragma unroll
            for (int i = 0; i < 4; i++) sacc[nt][i] = 0.f;

        #pragma unroll
        for (int ks = 0; ks < 8; ks++) {
            int rk = ks * 16 + ((lane >> 3) & 1) * 8 + (lane & 7);
            int ncb = ((lane >> 4) & 1) * 8;
            #pragma unroll
            for (int ng = 0; ng < 4; ng++) {
                int nc = ng * 16 + ncb;
                u32 koff = rk * 128 + ((((nc >> 3) ^ (rk & 7)) & 7) << 4);
                u32 kh_[4];
                ldsm4t(kh_, smaddr(Kh + koff));
                mma(sacc[2 * ng],     qf[ks], &kh_[0]);
                mma(sacc[2 * ng + 1], qf[ks], &kh_[2]);
            }
        }

        // ---- softmax, static max (p = 2^s) ----
        u32 ph[8][2];
        #pragma unroll
        for (int nt = 0; nt < 8; nt++) {
            float p0 = ex2(sacc[nt][0]);
            float p1 = ex2(sacc[nt][1]);
            float p2 = ex2(sacc[nt][2]);
            float p3 = ex2(sacc[nt][3]);
            l0r += p0 + p1; l1r += p2 + p3;
            ph[nt][0] = packbf(p0, p1);
            ph[nt][1] = packbf(p2, p3);
        }

        // ---- O += P V ----
        #pragma unroll
        for (int ks2 = 0; ks2 < 4; ks2++) {
            u32 pah[4] = {ph[2*ks2][0], ph[2*ks2][1], ph[2*ks2+1][0], ph[2*ks2+1][1]};
            int kc = ks2 * 16 + ((lane >> 3) & 1) * 8;
            int rvb = ((lane >> 4) & 1) * 8 + (lane & 7);
            #pragma unroll
            for (int nd = 0; nd < 8; nd++) {
                int rv = nd * 16 + rvb;
                u32 voff = rv * 128 + ((((kc >> 3) ^ (rv & 7)) & 7) << 4);
                u32 vh_[4];
                ldsm4(vh_, smaddr(Vh + voff));
                mma(oac[2 * nd],     pah, &vh_[0]);
                mma(oac[2 * nd + 1], pah, &vh_[2]);
            }
        }
        __syncthreads();
    }

    // ---- row-sum reduction (once) ----
    l0r += __shfl_xor_sync(0xffffffffu, l0r, 1);
    l0r += __shfl_xor_sync(0xffffffffu, l0r, 2);
    l1r += __shfl_xor_sync(0xffffffffu, l1r, 1);
    l1r += __shfl_xor_sync(0xffffffffu, l1r, 2);

    // ---- normalize + transpose (reuse stage smem) + store bf16 ----
    float inv0 = 1.f / l0r, inv1 = 1.f / l1r;
    float* Osm = (float*)(sm + 16384);  // [64 s][64 d] pitch 65 (16.6KB)
    const int r0 = wid * 16 + (lane >> 2), c2 = (lane & 3) * 2;
    #pragma unroll
    for (int dh = 0; dh < 2; dh++) {
        __syncthreads();
        #pragma unroll
        for (int j = 0; j < 8; j++) {
            int nt = dh * 8 + j;
            int dloc = j * 8 + c2;
            Osm[r0 * 65 + dloc]           = oac[nt][0] * inv0;
            Osm[r0 * 65 + dloc + 1]       = oac[nt][1] * inv0;
            Osm[(r0 + 8) * 65 + dloc]     = oac[nt][2] * inv1;
            Osm[(r0 + 8) * 65 + dloc + 1] = oac[nt][3] * inv1;
        }
        __syncthreads();
        for (int ch = tid; ch < 512; ch += 128) {
            int dl = ch >> 3, g = ch & 7;
            float f[8];
            #pragma unroll
            for (int j = 0; j < 8; j++) f[j] = Osm[(g * 8 + j) * 65 + dl];
            uint4 H;
            H.x = packbf(f[0], f[1]);
            H.y = packbf(f[2], f[3]);
            H.z = packbf(f[4], f[5]);
            H.w = packbf(f[6], f[7]);
            int c = h * 128 + dh * 64 + dl;
            size_t ga = ((size_t)b * C + c) * HW + s0q + g * 8;
            *(uint4*)(g_aoh + ga) = H;
        }
    }
}

// ---------------- launch ----------------
extern "C" void kernel_launch(void* const* d_in, const int* in_sizes, int n_in,
                              void* d_out, int out_size) {
    const float* x   = (const float*)d_in[0];
    const float* gnw = (const float*)d_in[1];
    const float* gnb = (const float*)d_in[2];
    const float* wq  = (const float*)d_in[3];
    const float* bq  = (const float*)d_in[4];
    const float* wk  = (const float*)d_in[5];
    const float* bk  = (const float*)d_in[6];
    const float* wv  = (const float*)d_in[7];
    const float* bv  = (const float*)d_in[8];
    const float* wp  = (const float*)d_in[9];
    const float* bp  = (const float*)d_in[10];
    float* out = (float*)d_out;

    cudaFuncSetAttribute(attn_mma_kernel,
                         cudaFuncAttributeMaxDynamicSharedMemorySize, ATT_SMEM);
    cudaFuncSetAttribute(conv_mma_kernel<0>,
                         cudaFuncAttributeMaxDynamicSharedMemorySize, CONV_SMEM);
    cudaFuncSetAttribute(conv_mma_kernel<1>,
                         cudaFuncAttributeMaxDynamicSharedMemorySize, CONV_SMEM);

    bf16 *d_xh, *d_aoh;
    cudaGetSymbolAddress((void**)&d_xh,  g_xh);
    cudaGetSymbolAddress((void**)&d_aoh, g_aoh);

    gn_stats_kernel<<<BATCH * NGROUPS, 256>>>(x);
    wprep_kernel<<<4096, 256>>>(wq, wk, wv, wp);
    xnorm_kernel<<<BATCH * C, 256>>>(x, gnw, gnb);
    conv_mma_kernel<0><<<dim3(HW / 64, 12, BATCH), 128, CONV_SMEM>>>(
        d_xh, bq, bk, bv, bp, x, nullptr);
    attn_mma_kernel<<<dim3(HW / 64, NHEADS, BATCH), 128, ATT_SMEM>>>();
    conv_mma_kernel<1><<<dim3(HW / 64, 4, BATCH), 128, CONV_SMEM>>>(
        d_aoh, bq, bk, bv, bp, x, out);
}

// round 17
// speedup vs baseline: 1.1336x; 1.0542x over previous
#include <cuda_runtime.h>
#include <cuda_bf16.h>
#include <math.h>

#define BATCH   4
#define C       512
#define HW      4096
#define NHEADS  4
#define HD      128
#define NGROUPS 32
#define EPS     1e-5f
// (1/sqrt(128)) * log2(e)
#define SCL2    0.12751743038311f

typedef unsigned u32;
typedef __nv_bfloat16  bf16;
typedef __nv_bfloat162 bf162;

// ---------------- scratch ----------------
__device__ float g_mean[BATCH * NGROUPS];
__device__ float g_rstd[BATCH * NGROUPS];
// normalized input bf16, layout [b][c][s]
__device__ __align__(16) bf16 g_xh[BATCH * C * HW];
// q/k/v bf16, layout [b][h][d][s]   (q pre-scaled by SCL2)
__device__ __align__(16) bf16 g_qh[BATCH * C * HW];
__device__ __align__(16) bf16 g_kh[BATCH * C * HW];
__device__ __align__(16) bf16 g_vh[BATCH * C * HW];
// attention out bf16, layout [b][c][s]
__device__ __align__(16) bf16 g_aoh[BATCH * C * HW];
// stacked bf16 weights: rows 0..511 wq | 512 wk | 1024 wv | 1536 wp
__device__ __align__(16) bf16 g_wh[2048 * C];

// ---------------- helpers ----------------
__device__ __forceinline__ u32 smaddr(const void* p) {
    return (u32)__cvta_generic_to_shared(p);
}
__device__ __forceinline__ void cpa16(u32 dst, const void* src) {
    asm volatile("cp.async.cg.shared.global [%0], [%1], 16;" :: "r"(dst), "l"(src));
}
__device__ __forceinline__ void cpa_commit() {
    asm volatile("cp.async.commit_group;");
}
template <int N>
__device__ __forceinline__ void cpa_wait() {
    asm volatile("cp.async.wait_group %0;" :: "n"(N));
}
__device__ __forceinline__ void ldsm4(u32* r, u32 a) {
    asm volatile("ldmatrix.sync.aligned.m8n8.x4.shared.b16 {%0,%1,%2,%3},[%4];"
        : "=r"(r[0]), "=r"(r[1]), "=r"(r[2]), "=r"(r[3]) : "r"(a));
}
__device__ __forceinline__ void ldsm4t(u32* r, u32 a) {
    asm volatile("ldmatrix.sync.aligned.m8n8.x4.trans.shared.b16 {%0,%1,%2,%3},[%4];"
        : "=r"(r[0]), "=r"(r[1]), "=r"(r[2]), "=r"(r[3]) : "r"(a));
}
__device__ __forceinline__ void mma(float* d, const u32* a, const u32* b) {
    asm volatile("mma.sync.aligned.m16n8k16.row.col.f32.bf16.bf16.f32 "
        "{%0,%1,%2,%3},{%4,%5,%6,%7},{%8,%9},{%0,%1,%2,%3};"
        : "+f"(d[0]), "+f"(d[1]), "+f"(d[2]), "+f"(d[3])
        : "r"(a[0]), "r"(a[1]), "r"(a[2]), "r"(a[3]), "r"(b[0]), "r"(b[1]));
}
__device__ __forceinline__ u32 packbf(float a, float b) {
    bf162 t = __floats2bfloat162_rn(a, b);
    return *(u32*)&t;
}
__device__ __forceinline__ float ex2(float x) {
    float r; asm("ex2.approx.f32 %0, %1;" : "=f"(r) : "f"(x)); return r;
}

// ---------------- GroupNorm statistics ----------------
__global__ void __launch_bounds__(256) gn_stats_kernel(const float* __restrict__ x) {
    const int bg = blockIdx.x;
    const float4* p = (const float4*)(x + (size_t)bg * (16 * HW));
    float s = 0.f, s2 = 0.f;
    for (int i = threadIdx.x; i < (16 * HW) / 4; i += 256) {
        float4 v = p[i];
        s  += (v.x + v.y) + (v.z + v.w);
        s2 += v.x*v.x + v.y*v.y + v.z*v.z + v.w*v.w;
    }
    #pragma unroll
    for (int off = 16; off; off >>= 1) {
        s  += __shfl_xor_sync(0xffffffffu, s,  off);
        s2 += __shfl_xor_sync(0xffffffffu, s2, off);
    }
    __shared__ float ss[8], ss2[8];
    const int w = threadIdx.x >> 5, l = threadIdx.x & 31;
    if (l == 0) { ss[w] = s; ss2[w] = s2; }
    __syncthreads();
    if (threadIdx.x == 0) {
        float S = 0.f, S2 = 0.f;
        #pragma unroll
        for (int i = 0; i < 8; i++) { S += ss[i]; S2 += ss2[i]; }
        const float inv = 1.f / (16.f * HW);
        float mean = S * inv;
        float var  = S2 * inv - mean * mean;
        g_mean[bg] = mean;
        g_rstd[bg] = rsqrtf(var + EPS);
    }
}

// ---------------- weight convert (bf16) ----------------
__global__ void __launch_bounds__(256) wprep_kernel(
    const float* __restrict__ wq, const float* __restrict__ wk,
    const float* __restrict__ wv, const float* __restrict__ wp)
{
    int i = blockIdx.x * 256 + threadIdx.x;    // 2048*512
    int r = i >> 9, c = i & 511;
    const float* srcs[4] = {wq, wk, wv, wp};
    float v = srcs[r >> 9][(r & 511) * C + c];
    g_wh[i] = __float2bfloat16(v);
}

// ---------------- normalize x -> bf16 ----------------
__global__ void __launch_bounds__(256) xnorm_kernel(
    const float* __restrict__ x,
    const float* __restrict__ gnw, const float* __restrict__ gnb)
{
    const int bc = blockIdx.x;                // b*C + c
    const int b = bc >> 9, c = bc & 511;
    const int grp = c >> 4;
    const float mu = g_mean[b * NGROUPS + grp], rs = g_rstd[b * NGROUPS + grp];
    const float sc = rs * gnw[c], sh = gnb[c] - mu * sc;
    const float* xp = x + (size_t)bc * HW;
    bf16* oh = g_xh + (size_t)bc * HW;
    for (int i = threadIdx.x * 4; i < HW; i += 1024) {
        float4 v = *(const float4*)(xp + i);
        uint2 H;
        H.x = packbf(fmaf(v.x, sc, sh), fmaf(v.y, sc, sh));
        H.y = packbf(fmaf(v.z, sc, sh), fmaf(v.w, sc, sh));
        *(uint2*)(oh + i) = H;
    }
}

// ---------------- conv GEMM: 128m x 64n tile, 128 thr ----------------------
// stage layout: Ah 10240 | Bh 4096 = 14336 B
#define CONV_STAGE 14336
#define CONV_SMEM  (2 * CONV_STAGE)

template <int EPI>
__global__ void __launch_bounds__(128) conv_mma_kernel(
    const bf16* __restrict__ BH,
    const float* __restrict__ bq, const float* __restrict__ bk,
    const float* __restrict__ bv, const float* __restrict__ bp,
    const float* __restrict__ resid, float* __restrict__ outp)
{
    extern __shared__ char smem[];
    const int tid = threadIdx.x, lane = tid & 31, wm = tid >> 5;  // 4 warps
    const int b = blockIdx.z;
    const int oBase = (EPI ? 1536 : 0) + blockIdx.y * 128;
    const int sBase = blockIdx.x * 64;

    auto load_stage = [&](int kb, int s) {
        char* Ah = smem + s * CONV_STAGE;
        char* Bh = Ah + 10240;
        #pragma unroll
        for (int ch = tid; ch < 512; ch += 128) {
            int row = ch >> 2, g = ch & 3;
            size_t ga = (size_t)(oBase + row) * C + kb + g * 8;
            cpa16(smaddr(Ah + row * 80 + g * 16), g_wh + ga);
        }
        #pragma unroll
        for (int ch = tid; ch < 256; ch += 128) {
            int k = ch >> 3, g = ch & 7;
            size_t ga = ((size_t)b * C + kb + k) * HW + sBase + g * 8;
            u32 d = k * 128 + (((g ^ (k & 7)) & 7) << 4);
            cpa16(smaddr(Bh + d), BH + ga);
        }
    };

    float acc[2][8][4];
    #pragma unroll
    for (int mt = 0; mt < 2; mt++)
        #pragma unroll
        for (int nt = 0; nt < 8; nt++)
            #pragma unroll
            for (int i = 0; i < 4; i++) acc[mt][nt][i] = 0.f;

    load_stage(0, 0);
    cpa_commit();

    for (int it = 0; it < 16; it++) {
        if (it + 1 < 16) load_stage((it + 1) * 32, (it + 1) & 1);
        cpa_commit();
        cpa_wait<1>();
        __syncthreads();

        char* Ah = smem + (it & 1) * CONV_STAGE;
        char* Bh = Ah + 10240;

        #pragma unroll
        for (int kk = 0; kk < 32; kk += 16) {
            u32 ah[2][4];
            #pragma unroll
            for (int mt = 0; mt < 2; mt++) {
                int row = wm * 32 + mt * 16 + (lane & 15);
                u32 off = row * 80 + ((kk >> 3) + (lane >> 4)) * 16;
                ldsm4(ah[mt], smaddr(Ah + off));
            }
            #pragma unroll
            for (int ng = 0; ng < 4; ng++) {
                int row = kk + ((lane >> 3) & 1) * 8 + (lane & 7);
                int nc  = ng * 16 + ((lane >> 4) & 1) * 8;
                u32 off = row * 128 + ((((nc >> 3) ^ (row & 7)) & 7) << 4);
                u32 bh_[4];
                ldsm4t(bh_, smaddr(Bh + off));
                #pragma unroll
                for (int mt = 0; mt < 2; mt++) {
                    mma(acc[mt][2 * ng],     ah[mt], &bh_[0]);
                    mma(acc[mt][2 * ng + 1], ah[mt], &bh_[2]);
                }
            }
        }
        __syncthreads();
    }

    // epilogue
    const int gr = lane >> 2, c2 = (lane & 3) * 2;
    if constexpr (EPI == 0) {
        const int mat  = blockIdx.y >> 2;
        const int head = blockIdx.y & 3;
        bf16* DH = (mat == 0) ? g_qh : (mat == 1) ? g_kh : g_vh;
        const float* bias = (mat == 0) ? bq : (mat == 1) ? bk : bv;
        const float osc = (mat == 0) ? SCL2 : 1.0f;    // fold softmax scale into q
        const size_t hb = (size_t)(b * NHEADS + head) * HD * HW;
        #pragma unroll
        for (int mt = 0; mt < 2; mt++) {
            int d0 = wm * 32 + mt * 16 + gr;
            float bs0 = bias[head * HD + d0];
            float bs1 = bias[head * HD + d0 + 8];
            #pragma unroll
            for (int nt = 0; nt < 8; nt++) {
                int s = sBase + nt * 8 + c2;
                *(u32*)(DH + hb + (size_t)d0 * HW + s) =
                    packbf((acc[mt][nt][0] + bs0) * osc, (acc[mt][nt][1] + bs0) * osc);
                *(u32*)(DH + hb + (size_t)(d0 + 8) * HW + s) =
                    packbf((acc[mt][nt][2] + bs1) * osc, (acc[mt][nt][3] + bs1) * osc);
            }
        }
    } else {
        const int cB = blockIdx.y * 128;
        #pragma unroll
        for (int mt = 0; mt < 2; mt++) {
            int ca = cB + wm * 32 + mt * 16 + gr;
            float bsa = bp[ca], bsb = bp[ca + 8];
            #pragma unroll
            for (int nt = 0; nt < 8; nt++) {
                int s = sBase + nt * 8 + c2;
                size_t ia = ((size_t)b * C + ca) * HW + s;
                size_t ib = ia + (size_t)8 * HW;
                float2 ra = *(const float2*)(resid + ia);
                float2 rb = *(const float2*)(resid + ib);
                *(float2*)(outp + ia) = make_float2(acc[mt][nt][0] + bsa + ra.x,
                                                    acc[mt][nt][1] + bsa + ra.y);
                *(float2*)(outp + ib) = make_float2(acc[mt][nt][2] + bsb + rb.x,
                                                    acc[mt][nt][3] + bsb + rb.y);
            }
        }
    }
}

// ---------------- flash attention: 64-row Q, Q-smem reuse, 3 CTAs/SM -------
// smem: 64K total. Q loads into [0,16K) then is reclaimed by stage slot0.
// stages: slot0 = [0,32K), slot1 = [32K,64K); kt uses slot (kt&1)^1.
#define ATT_STAGE 32768
#define ATT_SMEM  65536
#define NKT       (HW / 64)

__global__ void __launch_bounds__(128, 3) attn_mma_kernel() {
    extern __shared__ char sm[];

    const int tid = threadIdx.x, lane = tid & 31, wid = tid >> 5;   // wid 0..3
    const int qt = blockIdx.x, h = blockIdx.y, b = blockIdx.z;
    const size_t hb = (size_t)(b * NHEADS + h) * HD * HW;
    const int s0q = qt * 64;

    auto load_kv = [&](int kt, int slot) {
        char* Kh = sm + slot * ATT_STAGE;
        char* Vh = Kh + 16384;
        #pragma unroll
        for (int ch = tid; ch < 1024; ch += 128) {
            int d = ch >> 3, g = ch & 7;
            size_t ga = hb + (size_t)d * HW + kt * 64 + g * 8;
            u32 off = d * 128 + (((g ^ (d & 7)) & 7) << 4);
            cpa16(smaddr(Kh + off), g_kh + ga);
            cpa16(smaddr(Vh + off), g_vh + ga);
        }
    };

    // group 0: Q into [0,16K) ; group 1: kv0 into slot1 [32K,64K)
    #pragma unroll
    for (int ch = tid; ch < 1024; ch += 128) {
        int d = ch >> 3, g = ch & 7;
        size_t ga = hb + (size_t)d * HW + s0q + g * 8;
        u32 off = d * 128 + (((g ^ (d & 7)) & 7) << 4);
        cpa16(smaddr(sm + off), g_qh + ga);
    }
    cpa_commit();
    load_kv(0, 1);
    cpa_commit();

    // wait for Q only (group1 may still be in flight)
    cpa_wait<1>();
    __syncthreads();

    // hoist Q fragments (A of S; m = 16 rows per warp)
    u32 qf[8][4];
    {
        int mc = wid * 16 + ((lane >> 3) & 1) * 8;
        #pragma unroll
        for (int ks = 0; ks < 8; ks++) {
            int rq = ks * 16 + (lane & 7) + ((lane >> 4) & 1) * 8;
            u32 qoff = rq * 128 + ((((mc >> 3) ^ (rq & 7)) & 7) << 4);
            ldsm4t(qf[ks], smaddr(sm + qoff));
        }
    }
    __syncthreads();   // everyone has consumed Q; slot0 may now be overwritten

    float oac[16][4];
    #pragma unroll
    for (int nt = 0; nt < 16; nt++)
        #pragma unroll
        for (int i = 0; i < 4; i++) oac[nt][i] = 0.f;
    float l0r = 0.f, l1r = 0.f;

    for (int kt = 0; kt < NKT; kt++) {
        if (kt + 1 < NKT) load_kv(kt + 1, ((kt + 1) & 1) ^ 1);
        cpa_commit();
        cpa_wait<1>();
        __syncthreads();

        char* Kh = sm + ((kt & 1) ^ 1) * ATT_STAGE;
        char* Vh = Kh + 16384;

        // ---- S = Q K^T (q pre-scaled, bf16) ----
        float sacc[8][4];
        #pragma unroll
        for (int nt = 0; nt < 8; nt++)
            #pragma unroll
            for (int i = 0; i < 4; i++) sacc[nt][i] = 0.f;

        #pragma unroll
        for (int ks = 0; ks < 8; ks++) {
            int rk = ks * 16 + ((lane >> 3) & 1) * 8 + (lane & 7);
            int ncb = ((lane >> 4) & 1) * 8;
            #pragma unroll
            for (int ng = 0; ng < 4; ng++) {
                int nc = ng * 16 + ncb;
                u32 koff = rk * 128 + ((((nc >> 3) ^ (rk & 7)) & 7) << 4);
                u32 kh_[4];
                ldsm4t(kh_, smaddr(Kh + koff));
                mma(sacc[2 * ng],     qf[ks], &kh_[0]);
                mma(sacc[2 * ng + 1], qf[ks], &kh_[2]);
            }
        }

        // ---- softmax, static max (p = 2^s) ----
        u32 ph[8][2];
        #pragma unroll
        for (int nt = 0; nt < 8; nt++) {
            float p0 = ex2(sacc[nt][0]);
            float p1 = ex2(sacc[nt][1]);
            float p2 = ex2(sacc[nt][2]);
            float p3 = ex2(sacc[nt][3]);
            l0r += p0 + p1; l1r += p2 + p3;
            ph[nt][0] = packbf(p0, p1);
            ph[nt][1] = packbf(p2, p3);
        }

        // ---- O += P V ----
        #pragma unroll
        for (int ks2 = 0; ks2 < 4; ks2++) {
            u32 pah[4] = {ph[2*ks2][0], ph[2*ks2][1], ph[2*ks2+1][0], ph[2*ks2+1][1]};
            int kc = ks2 * 16 + ((lane >> 3) & 1) * 8;
            int rvb = ((lane >> 4) & 1) * 8 + (lane & 7);
            #pragma unroll
            for (int nd = 0; nd < 8; nd++) {
                int rv = nd * 16 + rvb;
                u32 voff = rv * 128 + ((((kc >> 3) ^ (rv & 7)) & 7) << 4);
                u32 vh_[4];
                ldsm4(vh_, smaddr(Vh + voff));
                mma(oac[2 * nd],     pah, &vh_[0]);
                mma(oac[2 * nd + 1], pah, &vh_[2]);
            }
        }
        __syncthreads();
    }

    // ---- row-sum reduction (once) ----
    l0r += __shfl_xor_sync(0xffffffffu, l0r, 1);
    l0r += __shfl_xor_sync(0xffffffffu, l0r, 2);
    l1r += __shfl_xor_sync(0xffffffffu, l1r, 1);
    l1r += __shfl_xor_sync(0xffffffffu, l1r, 2);

    // ---- normalize + transpose (reuse smem) + store bf16 ----
    float inv0 = 1.f / l0r, inv1 = 1.f / l1r;
    float* Osm = (float*)sm;            // [64 s][64 d] pitch 65 (16.6KB)
    const int r0 = wid * 16 + (lane >> 2), c2 = (lane & 3) * 2;
    #pragma unroll
    for (int dh = 0; dh < 2; dh++) {
        __syncthreads();
        #pragma unroll
        for (int j = 0; j < 8; j++) {
            int nt = dh * 8 + j;
            int dloc = j * 8 + c2;
            Osm[r0 * 65 + dloc]           = oac[nt][0] * inv0;
            Osm[r0 * 65 + dloc + 1]       = oac[nt][1] * inv0;
            Osm[(r0 + 8) * 65 + dloc]     = oac[nt][2] * inv1;
            Osm[(r0 + 8) * 65 + dloc + 1] = oac[nt][3] * inv1;
        }
        __syncthreads();
        for (int ch = tid; ch < 512; ch += 128) {
            int dl = ch >> 3, g = ch & 7;
            float f[8];
            #pragma unroll
            for (int j = 0; j < 8; j++) f[j] = Osm[(g * 8 + j) * 65 + dl];
            uint4 H;
            H.x = packbf(f[0], f[1]);
            H.y = packbf(f[2], f[3]);
            H.z = packbf(f[4], f[5]);
            H.w = packbf(f[6], f[7]);
            int c = h * 128 + dh * 64 + dl;
            size_t ga = ((size_t)b * C + c) * HW + s0q + g * 8;
            *(uint4*)(g_aoh + ga) = H;
        }
    }
}

// ---------------- launch ----------------
extern "C" void kernel_launch(void* const* d_in, const int* in_sizes, int n_in,
                              void* d_out, int out_size) {
    const float* x   = (const float*)d_in[0];
    const float* gnw = (const float*)d_in[1];
    const float* gnb = (const float*)d_in[2];
    const float* wq  = (const float*)d_in[3];
    const float* bq  = (const float*)d_in[4];
    const float* wk  = (const float*)d_in[5];
    const float* bk  = (const float*)d_in[6];
    const float* wv  = (const float*)d_in[7];
    const float* bv  = (const float*)d_in[8];
    const float* wp  = (const float*)d_in[9];
    const float* bp  = (const float*)d_in[10];
    float* out = (float*)d_out;

    cudaFuncSetAttribute(attn_mma_kernel,
                         cudaFuncAttributeMaxDynamicSharedMemorySize, ATT_SMEM);
    cudaFuncSetAttribute(conv_mma_kernel<0>,
                         cudaFuncAttributeMaxDynamicSharedMemorySize, CONV_SMEM);
    cudaFuncSetAttribute(conv_mma_kernel<1>,
                         cudaFuncAttributeMaxDynamicSharedMemorySize, CONV_SMEM);

    bf16 *d_xh, *d_aoh;
    cudaGetSymbolAddress((void**)&d_xh,  g_xh);
    cudaGetSymbolAddress((void**)&d_aoh, g_aoh);

    gn_stats_kernel<<<BATCH * NGROUPS, 256>>>(x);
    wprep_kernel<<<4096, 256>>>(wq, wk, wv, wp);
    xnorm_kernel<<<BATCH * C, 256>>>(x, gnw, gnb);
    conv_mma_kernel<0><<<dim3(HW / 64, 12, BATCH), 128, CONV_SMEM>>>(
        d_xh, bq, bk, bv, bp, x, nullptr);
    attn_mma_kernel<<<dim3(HW / 64, NHEADS, BATCH), 128, ATT_SMEM>>>();
    conv_mma_kernel<1><<<dim3(HW / 64, 4, BATCH), 128, CONV_SMEM>>>(
        d_aoh, bq, bk, bv, bp, x, out);
}